// round 2
// baseline (speedup 1.0000x reference)
#include <cuda_runtime.h>
#include <cstdint>

// Problem: out[b,s,:] = 1 / where(dmat[row,:]==0, BIG, dmat[row,:])
//   row = venueid2coor[inputs_poi[b,s]]
// N_POI=10000, V=20000, B=64, S=100, BIG=9999999.99
// Inputs (metadata order):
//   d_in[0]: venueid2coor  int   [20000]   (int32 under default JAX; detect int64)
//   d_in[1]: inputs_poi    int   [6400]
//   d_in[2]: poi_distance  f32   [10000*10000]
// Output: f32 [6400*10000]

#define N_POI 10000
#define N_VEC (N_POI / 4)   // 2500 float4 per row

__device__ int g_poi_is64;
__device__ int g_v2c_is64;

// Detect whether an integer buffer is int64 (LE, small nonneg values => all
// odd 32-bit words zero) or int32. Sampling 16 odd words: P(false positive
// with random int32 in [0,20000)) ~ (1/20000)^16 ~ 0.
__global__ void detect_dtype_kernel(const unsigned int* poi,
                                    const unsigned int* v2c)
{
    if (threadIdx.x == 0 && blockIdx.x == 0) {
        int poi64 = 1, v2c64 = 1;
        #pragma unroll
        for (int i = 1; i < 32; i += 2) {   // words 1..31: within 6400 elems either way
            if (poi[i] != 0u) poi64 = 0;
            if (v2c[i] != 0u) v2c64 = 0;
        }
        g_poi_is64 = poi64;
        g_v2c_is64 = v2c64;
    }
}

__global__ void attn_loc_distance_kernel(
    const void* __restrict__ venueid2coor,
    const void* __restrict__ inputs_poi,
    const float* __restrict__ dmat,
    float*       __restrict__ out)
{
    __shared__ int s_row;
    const int t = blockIdx.x;                 // token index 0..6399
    if (threadIdx.x == 0) {
        long long vid;
        if (g_poi_is64) vid = ((const long long*)inputs_poi)[t];
        else            vid = ((const int*)inputs_poi)[t];
        if (vid < 0) vid = 0;
        if (vid >= 20000) vid = 19999;

        long long row;
        if (g_v2c_is64) row = ((const long long*)venueid2coor)[vid];
        else            row = ((const int*)venueid2coor)[vid];
        if (row < 0) row = 0;
        if (row >= N_POI) row = N_POI - 1;
        s_row = (int)row;
    }
    __syncthreads();

    const float4* __restrict__ src =
        reinterpret_cast<const float4*>(dmat + (size_t)s_row * N_POI);
    float4* __restrict__ dst =
        reinterpret_cast<float4*>(out + (size_t)t * N_POI);

    const float BIG = 9999999.99f;

    #pragma unroll 4
    for (int i = threadIdx.x; i < N_VEC; i += blockDim.x) {
        float4 v = src[i];
        float4 r;
        r.x = 1.0f / (v.x == 0.0f ? BIG : v.x);
        r.y = 1.0f / (v.y == 0.0f ? BIG : v.y);
        r.z = 1.0f / (v.z == 0.0f ? BIG : v.z);
        r.w = 1.0f / (v.w == 0.0f ? BIG : v.w);
        dst[i] = r;
    }
}

extern "C" void kernel_launch(void* const* d_in, const int* in_sizes, int n_in,
                              void* d_out, int out_size)
{
    const void*  venueid2coor = d_in[0];
    const void*  inputs_poi   = d_in[1];
    const float* dmat         = (const float*)d_in[2];
    float*       out          = (float*)d_out;

    detect_dtype_kernel<<<1, 32>>>((const unsigned int*)inputs_poi,
                                   (const unsigned int*)venueid2coor);

    const int n_tokens = in_sizes[1];         // 6400
    attn_loc_distance_kernel<<<n_tokens, 256>>>(venueid2coor, inputs_poi, dmat, out);
}

// round 4
// speedup vs baseline: 1.0297x; 1.0297x over previous
#include <cuda_runtime.h>
#include <cstdint>

// out[t,:] = 1 / where(dmat[row(t),:]==0, BIG, dmat[row(t),:])
//   row(t) = venueid2coor[inputs_poi[t]]
// N_POI=10000, V=20000, tokens=6400, BIG=9999999.99
// Strategy: dedupe the row gather. Per-row token lists, one CTA per row,
// read each unique row from DRAM exactly once, fan out writes.

#define N_POI    10000
#define V_SIZE   20000
#define N_TOK    6400
#define N_VEC    (N_POI / 4)     // 2500 float4 per row
#define MAX_BATCH 64

__device__ int g_head[N_POI];
__device__ int g_next[N_TOK];
__device__ int g_poi_is64;
__device__ int g_v2c_is64;

// Init head[] = -1; block 0 / thread 0 also detects int32 vs int64 layout
// (little-endian int64 of small nonneg values => odd 32-bit words all zero).
__global__ void init_kernel(const unsigned int* poi, const unsigned int* v2c)
{
    int i = blockIdx.x * blockDim.x + threadIdx.x;
    if (i < N_POI) g_head[i] = -1;
    if (i == 0) {
        int poi64 = 1, v2c64 = 1;
        #pragma unroll
        for (int k = 1; k < 32; k += 2) {
            if (poi[k] != 0u) poi64 = 0;
            if (v2c[k] != 0u) v2c64 = 0;
        }
        g_poi_is64 = poi64;
        g_v2c_is64 = v2c64;
    }
}

// Push each token onto its row's list.
__global__ void build_lists_kernel(const void* __restrict__ venueid2coor,
                                   const void* __restrict__ inputs_poi,
                                   int n_tok)
{
    int t = blockIdx.x * blockDim.x + threadIdx.x;
    if (t >= n_tok) return;

    long long vid = g_poi_is64 ? ((const long long*)inputs_poi)[t]
                               : (long long)((const int*)inputs_poi)[t];
    if (vid < 0) vid = 0;
    if (vid >= V_SIZE) vid = V_SIZE - 1;

    long long row = g_v2c_is64 ? ((const long long*)venueid2coor)[vid]
                               : (long long)((const int*)venueid2coor)[vid];
    if (row < 0) row = 0;
    if (row >= N_POI) row = N_POI - 1;

    g_next[t] = atomicExch(&g_head[(int)row], t);
}

// One CTA per matrix row. Empty rows exit; others read the row once and
// write the transformed result to every token mapped to this row.
__global__ void __launch_bounds__(256) fanout_kernel(
    const float* __restrict__ dmat,
    float*       __restrict__ out)
{
    const int row = blockIdx.x;
    int start = g_head[row];          // uniform read -> broadcast
    if (start < 0) return;

    __shared__ float4* s_dst[MAX_BATCH];
    __shared__ int s_n;
    __shared__ int s_nextstart;

    const float4* __restrict__ src =
        reinterpret_cast<const float4*>(dmat + (size_t)row * N_POI);
    const float BIG = 9999999.99f;

    while (start >= 0) {
        if (threadIdx.x == 0) {
            int n = 0, t = start;
            while (t >= 0 && n < MAX_BATCH) {
                s_dst[n++] = reinterpret_cast<float4*>(out + (size_t)t * N_POI);
                t = g_next[t];
            }
            s_n = n;
            s_nextstart = t;
        }
        __syncthreads();
        const int n = s_n;

        for (int i = threadIdx.x; i < N_VEC; i += 256) {
            float4 v = __ldg(&src[i]);
            float4 r;
            r.x = __frcp_rn(v.x == 0.0f ? BIG : v.x);
            r.y = __frcp_rn(v.y == 0.0f ? BIG : v.y);
            r.z = __frcp_rn(v.z == 0.0f ? BIG : v.z);
            r.w = __frcp_rn(v.w == 0.0f ? BIG : v.w);
            for (int j = 0; j < n; j++) {
                __stcs(&s_dst[j][i], r);   // streaming store: output never re-read
            }
        }
        start = s_nextstart;
        __syncthreads();
    }
}

extern "C" void kernel_launch(void* const* d_in, const int* in_sizes, int n_in,
                              void* d_out, int out_size)
{
    const void*  venueid2coor = d_in[0];
    const void*  inputs_poi   = d_in[1];
    const float* dmat         = (const float*)d_in[2];
    float*       out          = (float*)d_out;

    int n_tok = in_sizes[1];
    if (n_tok > N_TOK) n_tok = N_TOK;

    init_kernel<<<(N_POI + 255) / 256, 256>>>((const unsigned int*)inputs_poi,
                                              (const unsigned int*)venueid2coor);
    build_lists_kernel<<<(n_tok + 255) / 256, 256>>>(venueid2coor, inputs_poi, n_tok);
    fanout_kernel<<<N_POI, 256>>>(dmat, out);
}

// round 9
// speedup vs baseline: 1.1551x; 1.1217x over previous
#include <cuda_runtime.h>
#include <cstdint>

// out[t,:] = 1 / where(dmat[row(t),:]==0, BIG, dmat[row(t),:])
//   row(t) = venueid2coor[inputs_poi[t]]
// Dedup gather: per-row token lists; one CTA per (row, half-row segment);
// each unique row read from DRAM exactly once; fan out writes.

#define N_POI    10000
#define V_SIZE   20000
#define N_TOK    6400
#define MAX_BATCH 64

#define SEGMENTS 2
#define SEG_VEC  1250        // float4 per segment (2500 total per row)
#define FULL_IT  4           // 4*256 = 1024 vectors
#define TAIL     226         // 1250 - 1024

__device__ int g_head[N_POI];
__device__ int g_next[N_TOK];
__device__ int g_poi_is64;
__device__ int g_v2c_is64;

__global__ void init_kernel(const unsigned int* poi, const unsigned int* v2c)
{
    int i = blockIdx.x * blockDim.x + threadIdx.x;
    if (i < N_POI) g_head[i] = -1;
    if (i == 0) {
        int poi64 = 1, v2c64 = 1;
        #pragma unroll
        for (int k = 1; k < 32; k += 2) {      // LE int64 of small values -> odd words 0
            if (poi[k] != 0u) poi64 = 0;
            if (v2c[k] != 0u) v2c64 = 0;
        }
        g_poi_is64 = poi64;
        g_v2c_is64 = v2c64;
    }
}

__global__ void build_lists_kernel(const void* __restrict__ venueid2coor,
                                   const void* __restrict__ inputs_poi,
                                   int n_tok)
{
    int t = blockIdx.x * blockDim.x + threadIdx.x;
    if (t >= n_tok) return;

    long long vid = g_poi_is64 ? ((const long long*)inputs_poi)[t]
                               : (long long)((const int*)inputs_poi)[t];
    if (vid < 0) vid = 0;
    if (vid >= V_SIZE) vid = V_SIZE - 1;

    long long row = g_v2c_is64 ? ((const long long*)venueid2coor)[vid]
                               : (long long)((const int*)venueid2coor)[vid];
    if (row < 0) row = 0;
    if (row >= N_POI) row = N_POI - 1;

    g_next[t] = atomicExch(&g_head[(int)row], t);
}

__device__ __forceinline__ float4 xform(float4 v)
{
    const float BIG = 9999999.99f;
    float4 r;
    r.x = __frcp_rn(v.x == 0.0f ? BIG : v.x);
    r.y = __frcp_rn(v.y == 0.0f ? BIG : v.y);
    r.z = __frcp_rn(v.z == 0.0f ? BIG : v.z);
    r.w = __frcp_rn(v.w == 0.0f ? BIG : v.w);
    return r;
}

// grid = (N_POI, SEGMENTS), block = 256.
__global__ void __launch_bounds__(256) fanout_kernel(
    const float* __restrict__ dmat,
    float*       __restrict__ out)
{
    const int row = blockIdx.x;
    int start = g_head[row];                 // uniform -> broadcast
    if (start < 0) return;

    const int tid = threadIdx.x;
    const int segbase = blockIdx.y * SEG_VEC;

    const float4* __restrict__ src =
        reinterpret_cast<const float4*>(dmat + (size_t)row * N_POI) + segbase;

    __shared__ float4* s_dst[MAX_BATCH];
    __shared__ int s_n;
    __shared__ int s_next;

    while (start >= 0) {
        if (tid == 0) {
            int n = 0, t = start;
            while (t >= 0 && n < MAX_BATCH) {
                s_dst[n++] = reinterpret_cast<float4*>(out + (size_t)t * N_POI) + segbase;
                t = g_next[t];
            }
            s_n = n;
            s_next = t;
        }
        __syncthreads();
        const int n = s_n;

        if (n == 1) {
            float4* __restrict__ dst = s_dst[0];
            float4 v[FULL_IT];
            #pragma unroll
            for (int k = 0; k < FULL_IT; k++)          // 4 independent loads in flight
                v[k] = __ldcs(&src[tid + k * 256]);
            #pragma unroll
            for (int k = 0; k < FULL_IT; k++)
                __stcs(&dst[tid + k * 256], xform(v[k]));
            if (tid < TAIL) {
                float4 t4 = __ldcs(&src[FULL_IT * 256 + tid]);
                __stcs(&dst[FULL_IT * 256 + tid], xform(t4));
            }
        } else {
            float4 r[FULL_IT];
            #pragma unroll
            for (int k = 0; k < FULL_IT; k++)
                r[k] = __ldcs(&src[tid + k * 256]);
            #pragma unroll
            for (int k = 0; k < FULL_IT; k++)
                r[k] = xform(r[k]);
            float4 rt;
            if (tid < TAIL)
                rt = xform(__ldcs(&src[FULL_IT * 256 + tid]));
            for (int j = 0; j < n; j++) {
                float4* __restrict__ dst = s_dst[j];
                #pragma unroll
                for (int k = 0; k < FULL_IT; k++)
                    __stcs(&dst[tid + k * 256], r[k]);
                if (tid < TAIL)
                    __stcs(&dst[FULL_IT * 256 + tid], rt);
            }
        }
        start = s_next;
        __syncthreads();
    }
}

extern "C" void kernel_launch(void* const* d_in, const int* in_sizes, int n_in,
                              void* d_out, int out_size)
{
    const void*  venueid2coor = d_in[0];
    const void*  inputs_poi   = d_in[1];
    const float* dmat         = (const float*)d_in[2];
    float*       out          = (float*)d_out;

    int n_tok = in_sizes[1];
    if (n_tok > N_TOK) n_tok = N_TOK;

    init_kernel<<<(N_POI + 255) / 256, 256>>>((const unsigned int*)inputs_poi,
                                              (const unsigned int*)venueid2coor);
    build_lists_kernel<<<(n_tok + 255) / 256, 256>>>(venueid2coor, inputs_poi, n_tok);

    dim3 grid(N_POI, SEGMENTS);
    fanout_kernel<<<grid, 256>>>(dmat, out);
}